// round 1
// baseline (speedup 1.0000x reference)
#include <cuda_runtime.h>
#include <math.h>

#define HIDDEN 64
#define BATCH  16
#define TSTEPS 16
#define NNPOS  4096
#define OC     256
#define TILE_N 32
#define JP     8      // TILE_N / 4 quadrants
#define CH     8      // ic chunk staged in smem

// ---- persistent scratch (device globals; no allocation allowed) ----
__device__ float g_h0[BATCH * HIDDEN * NNPOS];
__device__ float g_h1[BATCH * HIDDEN * NNPOS];
__device__ float g_c [BATCH * HIDDEN * NNPOS];
__device__ float g_w [3 * 65 * OC];   // [kh][ic][oc]; ic 0..63 = h-channels, ic 64 = x

// Repack conv_w (OIHW, [256,65,3,3], only kw=1 matters) -> g_w[kh][ic][oc]
__global__ void repack_w(const float* __restrict__ conv_w) {
    int idx = blockIdx.x * blockDim.x + threadIdx.x;
    if (idx >= 3 * 65 * OC) return;
    int oc = idx & (OC - 1);
    int ic = (idx >> 8) % 65;
    int kh = idx / (65 * OC);
    int src_ic = (ic < 64) ? (ic + 1) : 0;   // input channel 0 of conv is x
    g_w[idx] = conv_w[((oc * 65 + src_ic) * 3 + kh) * 3 + 1];
}

__global__ void zero_state() {
    size_t i = (size_t)blockIdx.x * blockDim.x + threadIdx.x;
    size_t stride = (size_t)gridDim.x * blockDim.x;
    const size_t total = (size_t)BATCH * HIDDEN * NNPOS;
    for (; i < total; i += stride) { g_h0[i] = 0.f; g_c[i] = 0.f; }
}

__global__ void __launch_bounds__(256)
lstm_step(const float* __restrict__ x, const float* __restrict__ conv_b,
          int t, int parity) {
    const float* __restrict__ hin  = parity ? g_h1 : g_h0;
    float*       __restrict__ hout = parity ? g_h0 : g_h1;

    const int b   = blockIdx.y;
    const int n0  = blockIdx.x * TILE_N;
    const int tid = threadIdx.x;
    const int ch  = tid & 63;      // hidden channel
    const int q   = tid >> 6;      // position quadrant 0..3

    __shared__ float h_s[HIDDEN][TILE_N + 2];
    __shared__ float x_s[TILE_N + 2];
    __shared__ float w_s[3][CH][OC];

    // Load h halo tile [64][34]
    const float* hb = hin + (size_t)b * HIDDEN * NNPOS;
    for (int m = tid; m < HIDDEN * (TILE_N + 2); m += 256) {
        int ic = m / (TILE_N + 2);
        int j  = m % (TILE_N + 2);
        int n  = n0 - 1 + j;
        h_s[ic][j] = (n >= 0 && n < NNPOS) ? hb[(size_t)ic * NNPOS + n] : 0.f;
    }
    if (tid < TILE_N + 2) {
        int n = n0 - 1 + tid;
        x_s[tid] = (n >= 0 && n < NNPOS) ? x[((size_t)b * TSTEPS + t) * NNPOS + n] : 0.f;
    }

    float acc[4][JP];
    #pragma unroll
    for (int g = 0; g < 4; g++) {
        float bias = conv_b[g * 64 + ch];
        #pragma unroll
        for (int j = 0; j < JP; j++) acc[g][j] = bias;
    }

    const float* srcb = &h_s[0][0];  // keep base for computed row access

    // h-channel contributions, staged in SMEM chunks of CH ics
    #pragma unroll 1
    for (int c0 = 0; c0 < 64; c0 += CH) {
        __syncthreads();
        #pragma unroll
        for (int m = tid; m < 3 * CH * OC; m += 256) {
            int oc = m & (OC - 1);
            int r  = m >> 8;
            int ic = r % CH;
            int kh = r / CH;
            w_s[kh][ic][oc] = g_w[(kh * 65 + (c0 + ic)) * OC + oc];
        }
        __syncthreads();

        #pragma unroll 2
        for (int ii = 0; ii < CH; ii++) {
            const float* src = &h_s[c0 + ii][q * JP];
            float w[4][3];
            #pragma unroll
            for (int g = 0; g < 4; g++)
                #pragma unroll
                for (int kh = 0; kh < 3; kh++)
                    w[g][kh] = w_s[kh][ii][g * 64 + ch];
            float p0 = src[0], p1 = src[1];
            #pragma unroll
            for (int j = 0; j < JP; j++) {
                float p2 = src[j + 2];
                #pragma unroll
                for (int g = 0; g < 4; g++)
                    acc[g][j] += w[g][0] * p0 + w[g][1] * p1 + w[g][2] * p2;
                p0 = p1; p1 = p2;
            }
        }
    }
    (void)srcb;

    // x-channel contribution (ic index 64 in g_w)
    {
        float w[4][3];
        #pragma unroll
        for (int g = 0; g < 4; g++)
            #pragma unroll
            for (int kh = 0; kh < 3; kh++)
                w[g][kh] = g_w[(kh * 65 + 64) * OC + g * 64 + ch];
        const float* src = &x_s[q * JP];
        float p0 = src[0], p1 = src[1];
        #pragma unroll
        for (int j = 0; j < JP; j++) {
            float p2 = src[j + 2];
            #pragma unroll
            for (int g = 0; g < 4; g++)
                acc[g][j] += w[g][0] * p0 + w[g][1] * p1 + w[g][2] * p2;
            p0 = p1; p1 = p2;
        }
    }

    // LSTM elementwise, all in registers; c updated in place (exclusive per thread)
    size_t base = (size_t)b * HIDDEN * NNPOS + (size_t)ch * NNPOS + n0 + q * JP;
    #pragma unroll
    for (int j = 0; j < JP; j++) {
        float ig = 1.f / (1.f + expf(-acc[0][j]));
        float fg = 1.f / (1.f + expf(-acc[1][j]));
        float og = 1.f / (1.f + expf(-acc[2][j]));
        float gg = tanhf(acc[3][j]);
        float c2 = fg * g_c[base + j] + ig * gg;
        g_c[base + j]  = c2;
        hout[base + j] = og * tanhf(c2);
    }
}

// Final 1x1 conv over hidden dim + broadcast over TS
__global__ void __launch_bounds__(256)
fc_kernel(const float* __restrict__ fc_w, const float* __restrict__ fc_b,
          float* __restrict__ out) {
    __shared__ float w_s[HIDDEN];
    int tid = threadIdx.x;
    if (tid < HIDDEN) w_s[tid] = fc_w[tid];
    __syncthreads();

    int b = blockIdx.y;
    int n = blockIdx.x * 256 + tid;
    const float* hb = g_h0 + (size_t)b * HIDDEN * NNPOS + n;  // final h lives in g_h0
    float acc = fc_b[0];
    #pragma unroll
    for (int ch = 0; ch < HIDDEN; ch++)
        acc += hb[(size_t)ch * NNPOS] * w_s[ch];

    #pragma unroll
    for (int t = 0; t < TSTEPS; t++)
        out[((size_t)b * TSTEPS + t) * NNPOS + n] = acc;
}

extern "C" void kernel_launch(void* const* d_in, const int* in_sizes, int n_in,
                              void* d_out, int out_size) {
    const float* x      = (const float*)d_in[0];  // [16,16,4096,1]
    const float* conv_w = (const float*)d_in[1];  // [256,65,3,3]
    const float* conv_b = (const float*)d_in[2];  // [256]
    const float* fc_w   = (const float*)d_in[3];  // [1,64,1,1]
    const float* fc_b   = (const float*)d_in[4];  // [1]
    float* out = (float*)d_out;                   // [16,16,4096,1]

    repack_w<<<(3 * 65 * OC + 255) / 256, 256>>>(conv_w);
    zero_state<<<1024, 256>>>();

    dim3 grid(NNPOS / TILE_N, BATCH);
    for (int t = 0; t < TSTEPS; t++)
        lstm_step<<<grid, 256>>>(x, conv_b, t, t & 1);

    fc_kernel<<<dim3(NNPOS / 256, BATCH), 256>>>(fc_w, fc_b, out);
}

// round 2
// speedup vs baseline: 1.2749x; 1.2749x over previous
#include <cuda_runtime.h>
#include <math.h>

#define HIDDEN 64
#define BATCH  16
#define TSTEPS 16
#define NNPOS  4096
#define OC     256
#define TILE_N 64     // positions per block
#define CH     4      // ic chunk staged in smem
#define HPW    58     // packed-h entries per ic: i in [0,57]

typedef unsigned long long u64;

// ---- persistent scratch (device globals; no allocation allowed) ----
__device__ float g_h0[BATCH * HIDDEN * NNPOS];
__device__ float g_h1[BATCH * HIDDEN * NNPOS];
__device__ float g_c [BATCH * HIDDEN * NNPOS];
__device__ float g_w [3 * 65 * OC];   // [kh][ic][oc]; ic 0..63 = h-channels, ic 64 = x

// ---- packed fp32x2 helpers (FFMA2 path; ptxas never emits these from C++) ----
__device__ __forceinline__ u64 pk2(float lo, float hi) {
    u64 r; asm("mov.b64 %0,{%1,%2};" : "=l"(r) : "f"(lo), "f"(hi)); return r;
}
__device__ __forceinline__ u64 dup2(float v) { return pk2(v, v); }
__device__ __forceinline__ void unpk(u64 v, float& a, float& b) {
    asm("mov.b64 {%0,%1},%2;" : "=f"(a), "=f"(b) : "l"(v));
}
__device__ __forceinline__ void ffma2(u64& d, u64 a, u64 b) {
    asm("fma.rn.f32x2 %0,%1,%2,%0;" : "+l"(d) : "l"(a), "l"(b));
}

// Repack conv_w (OIHW, [256,65,3,3], only kw=1 matters) -> g_w[kh][ic][oc]
__global__ void repack_w(const float* __restrict__ conv_w) {
    int idx = blockIdx.x * blockDim.x + threadIdx.x;
    if (idx >= 3 * 65 * OC) return;
    int oc = idx & (OC - 1);
    int ic = (idx >> 8) % 65;
    int kh = idx / (65 * OC);
    int src_ic = (ic < 64) ? (ic + 1) : 0;   // input channel 0 of conv is x
    g_w[idx] = conv_w[((oc * 65 + src_ic) * 3 + kh) * 3 + 1];
}

__global__ void zero_state() {
    size_t i = (size_t)blockIdx.x * blockDim.x + threadIdx.x;
    size_t stride = (size_t)gridDim.x * blockDim.x;
    const size_t total = (size_t)BATCH * HIDDEN * NNPOS;
    for (; i < total; i += stride) { g_h0[i] = 0.f; g_c[i] = 0.f; }
}

__device__ __forceinline__ float fast_sigmoid(float x) {
    return 1.f / (1.f + __expf(-x));
}
__device__ __forceinline__ float fast_tanh(float x) {
    float e = __expf(-2.f * x);
    return (1.f - e) / (1.f + e);
}

__global__ void __launch_bounds__(256, 2)
lstm_step(const float* __restrict__ x, const float* __restrict__ conv_b,
          int t, int parity) {
    const float* __restrict__ hin  = parity ? g_h1 : g_h0;
    float*       __restrict__ hout = parity ? g_h0 : g_h1;

    const int b   = blockIdx.y;
    const int n0  = blockIdx.x * TILE_N;
    const int tid = threadIdx.x;
    const int ch  = tid & 63;      // hidden channel
    const int q   = tid >> 6;      // position quadrant (16 positions each)

    // hp_s[ic][i] = ( h[n0-1+i], h[n0+7+i] )  -> packed pair 8 positions apart
    __shared__ u64   hp_s[HIDDEN][HPW];
    __shared__ u64   xp_s[HPW];
    __shared__ float w_s[3][CH][OC];

    const float* hb = hin + (size_t)b * HIDDEN * NNPOS;
    for (int m = tid; m < HIDDEN * HPW; m += 256) {
        int ic = m / HPW;
        int i  = m % HPW;
        int nlo = n0 - 1 + i;
        int nhi = n0 + 7 + i;
        float lo = (nlo >= 0 && nlo < NNPOS) ? hb[(size_t)ic * NNPOS + nlo] : 0.f;
        float hi = (nhi < NNPOS)             ? hb[(size_t)ic * NNPOS + nhi] : 0.f;
        hp_s[ic][i] = pk2(lo, hi);
    }
    if (tid < HPW) {
        const float* xb = x + ((size_t)b * TSTEPS + t) * NNPOS;
        int nlo = n0 - 1 + tid;
        int nhi = n0 + 7 + tid;
        float lo = (nlo >= 0 && nlo < NNPOS) ? xb[nlo] : 0.f;
        float hi = (nhi < NNPOS)             ? xb[nhi] : 0.f;
        xp_s[tid] = pk2(lo, hi);
    }

    // accumulators: 4 gates x 8 packed position-pairs (16 positions)
    u64 acc[4][8];
    #pragma unroll
    for (int g = 0; g < 4; g++) {
        u64 bv = dup2(conv_b[g * 64 + ch]);
        #pragma unroll
        for (int j = 0; j < 8; j++) acc[g][j] = bv;
    }

    __syncthreads();   // hp_s / xp_s ready

    // x-channel contribution (ic index 64 in g_w); weights via global (L1-cached)
    {
        u64 xr[10];
        #pragma unroll
        for (int i = 0; i < 10; i++) xr[i] = xp_s[q * 16 + i];
        #pragma unroll
        for (int g = 0; g < 4; g++) {
            u64 w0 = dup2(g_w[(0 * 65 + 64) * OC + g * 64 + ch]);
            u64 w1 = dup2(g_w[(1 * 65 + 64) * OC + g * 64 + ch]);
            u64 w2 = dup2(g_w[(2 * 65 + 64) * OC + g * 64 + ch]);
            #pragma unroll
            for (int j = 0; j < 8; j++) {
                ffma2(acc[g][j], w0, xr[j]);
                ffma2(acc[g][j], w1, xr[j + 1]);
                ffma2(acc[g][j], w2, xr[j + 2]);
            }
        }
    }

    // h-channel contributions, weights staged in SMEM chunks of CH ics
    #pragma unroll 1
    for (int c0 = 0; c0 < 64; c0 += CH) {
        __syncthreads();
        #pragma unroll
        for (int m = tid; m < 3 * CH * OC; m += 256) {
            int oc = m & (OC - 1);
            int r  = m >> 8;        // 0..11
            int ii = r % CH;
            int kh = r / CH;
            w_s[kh][ii][oc] = g_w[(kh * 65 + (c0 + ii)) * OC + oc];
        }
        __syncthreads();

        #pragma unroll
        for (int ii = 0; ii < CH; ii++) {
            const int ic = c0 + ii;
            u64 hr[10];
            #pragma unroll
            for (int i = 0; i < 10; i++) hr[i] = hp_s[ic][q * 16 + i];
            #pragma unroll
            for (int g = 0; g < 4; g++) {
                u64 w0 = dup2(w_s[0][ii][g * 64 + ch]);
                u64 w1 = dup2(w_s[1][ii][g * 64 + ch]);
                u64 w2 = dup2(w_s[2][ii][g * 64 + ch]);
                #pragma unroll
                for (int j = 0; j < 8; j++) {
                    ffma2(acc[g][j], w0, hr[j]);
                    ffma2(acc[g][j], w1, hr[j + 1]);
                    ffma2(acc[g][j], w2, hr[j + 2]);
                }
            }
        }
    }

    // LSTM elementwise; lanes map to positions (p, p+8); c updated in place
    size_t base = (size_t)b * HIDDEN * NNPOS + (size_t)ch * NNPOS + n0 + q * 16;
    #pragma unroll
    for (int j = 0; j < 8; j++) {
        float i0, i1, f0, f1, o0, o1, g0, g1;
        unpk(acc[0][j], i0, i1);
        unpk(acc[1][j], f0, f1);
        unpk(acc[2][j], o0, o1);
        unpk(acc[3][j], g0, g1);
        {
            float ig = fast_sigmoid(i0), fg = fast_sigmoid(f0), og = fast_sigmoid(o0);
            float gg = fast_tanh(g0);
            float c2 = fg * g_c[base + j] + ig * gg;
            g_c[base + j]  = c2;
            hout[base + j] = og * fast_tanh(c2);
        }
        {
            float ig = fast_sigmoid(i1), fg = fast_sigmoid(f1), og = fast_sigmoid(o1);
            float gg = fast_tanh(g1);
            float c2 = fg * g_c[base + j + 8] + ig * gg;
            g_c[base + j + 8]  = c2;
            hout[base + j + 8] = og * fast_tanh(c2);
        }
    }
}

// Final 1x1 conv over hidden dim + broadcast over TS
__global__ void __launch_bounds__(256)
fc_kernel(const float* __restrict__ fc_w, const float* __restrict__ fc_b,
          float* __restrict__ out) {
    __shared__ float w_s[HIDDEN];
    int tid = threadIdx.x;
    if (tid < HIDDEN) w_s[tid] = fc_w[tid];
    __syncthreads();

    int b = blockIdx.y;
    int n = blockIdx.x * 256 + tid;
    const float* hb = g_h0 + (size_t)b * HIDDEN * NNPOS + n;  // final h lives in g_h0
    float acc = fc_b[0];
    #pragma unroll
    for (int ch = 0; ch < HIDDEN; ch++)
        acc += hb[(size_t)ch * NNPOS] * w_s[ch];

    #pragma unroll
    for (int t = 0; t < TSTEPS; t++)
        out[((size_t)b * TSTEPS + t) * NNPOS + n] = acc;
}

extern "C" void kernel_launch(void* const* d_in, const int* in_sizes, int n_in,
                              void* d_out, int out_size) {
    const float* x      = (const float*)d_in[0];  // [16,16,4096,1]
    const float* conv_w = (const float*)d_in[1];  // [256,65,3,3]
    const float* conv_b = (const float*)d_in[2];  // [256]
    const float* fc_w   = (const float*)d_in[3];  // [1,64,1,1]
    const float* fc_b   = (const float*)d_in[4];  // [1]
    float* out = (float*)d_out;                   // [16,16,4096,1]

    repack_w<<<(3 * 65 * OC + 255) / 256, 256>>>(conv_w);
    zero_state<<<1024, 256>>>();

    dim3 grid(NNPOS / TILE_N, BATCH);
    for (int t = 0; t < TSTEPS; t++)
        lstm_step<<<grid, 256>>>(x, conv_b, t, t & 1);

    fc_kernel<<<dim3(NNPOS / 256, BATCH), 256>>>(fc_w, fc_b, out);
}